// round 7
// baseline (speedup 1.0000x reference)
#include <cuda_runtime.h>
#include <math.h>

#define LSEQ 9216
#define NCHK 96
#define TCH  96

// ------------------------- scratch (device globals) -------------------------
__device__ __align__(16) float g_Um [4*LSEQ*64];
__device__ __align__(16) float g_Z  [4*LSEQ*64];
__device__ __align__(16) float g_dm [4*LSEQ*64];
__device__ __align__(16) float g_BCm[4*LSEQ*32];
__device__ __align__(16) float g_ym [4*LSEQ*64];
__device__ __align__(16) float g_Ug [4*LSEQ*128];
__device__ __align__(16) float g_dg [4*LSEQ*128];
__device__ __align__(16) float g_BCg[4*LSEQ*32];
__device__ __align__(16) float g_yg [4*LSEQ*128];
__device__ __align__(16) float g_SumM[4*NCHK*64*32];
__device__ __align__(16) float g_SumG[4*NCHK*128*32];
__device__ __align__(16) float g_HinM[4*NCHK*64*16];
__device__ __align__(16) float g_HinG[4*NCHK*128*16];

__device__ __forceinline__ float siluf(float y) {
    return y / (1.f + __expf(-y));
}
__device__ __forceinline__ float softplusf(float x) {
    return (x > 20.f) ? x : log1pf(expf(x));
}
// pw[k] = e1^(k+1), k=0..15, log-depth multiply tree
__device__ __forceinline__ void powers16(float e1, float* pw) {
    pw[0]=e1;
    pw[1]=pw[0]*pw[0];  pw[2]=pw[1]*pw[0];  pw[3]=pw[1]*pw[1];
    pw[4]=pw[2]*pw[1];  pw[5]=pw[2]*pw[2];  pw[6]=pw[3]*pw[2];  pw[7]=pw[3]*pw[3];
    pw[8]=pw[4]*pw[3];  pw[9]=pw[4]*pw[4];  pw[10]=pw[5]*pw[4]; pw[11]=pw[5]*pw[5];
    pw[12]=pw[6]*pw[5]; pw[13]=pw[6]*pw[6]; pw[14]=pw[7]*pw[6]; pw[15]=pw[7]*pw[7];
}

// ---------------- mixer front: xz = s@Wi^T + bi ; dwconv(K=4) ; silu ---------
__global__ void __launch_bounds__(128) k_mixer_front(
    const float* __restrict__ f1, const float* __restrict__ f2,
    const float* __restrict__ Wi, const float* __restrict__ bi,
    const float* __restrict__ wcx, const float* __restrict__ bcx,
    const float* __restrict__ wcz, const float* __restrict__ bcz)
{
    const int TF = 64;
    __shared__ __align__(16) float sx[TF+3][64];
    int s = blockIdx.x;                       // seq: stream*2 + b
    const float* f = ((s >> 1) ? f2 : f1) + (size_t)(s & 1) * 64 * LSEQ;
    int l0 = blockIdx.y * TF;
    int tid = threadIdx.x;

    for (int idx = tid; idx < (TF+3)*64; idx += 128) {
        int c = idx & 63, j = idx >> 6;
        int gl = l0 - 1 + j;
        sx[j][c] = (gl >= 0 && gl < LSEQ) ? f[(size_t)c*LSEQ + gl] : 0.f;
    }
    __syncthreads();

    int c = tid;                              // output channel 0..127
    float w[64];
    #pragma unroll 16
    for (int k = 0; k < 64; k++) w[k] = Wi[c*64 + k];
    float bias = bi[c];
    const float* cw = (c < 64) ? (wcx + c*4) : (wcz + (c-64)*4);
    float cw0 = cw[0], cw1 = cw[1], cw2 = cw[2], cw3 = cw[3];
    float cb = (c < 64) ? bcx[c] : bcz[c-64];
    float* outp = (c < 64) ? (g_Um + (size_t)s*LSEQ*64 + c)
                           : (g_Z  + (size_t)s*LSEQ*64 + (c-64));
    float x0 = 0.f, x1 = 0.f, x2 = 0.f;
    for (int j = 0; j < TF+3; j++) {
        int gl = l0 - 1 + j;
        float acc = bias;
        const float4* row = (const float4*)sx[j];
        #pragma unroll
        for (int k4 = 0; k4 < 16; k4++) {
            float4 v = row[k4];
            acc += v.x*w[4*k4] + v.y*w[4*k4+1] + v.z*w[4*k4+2] + v.w*w[4*k4+3];
        }
        if (gl < 0 || gl >= LSEQ) acc = 0.f;
        if (j >= 3) {
            float y = cw0*x0 + cw1*x1 + cw2*x2 + cw3*acc + cb;
            outp[(size_t)(l0 + j - 3) * 64] = siluf(y);
        }
        x0 = x1; x1 = x2; x2 = acc;
    }
}

// ---------- global front: h = s@Wg^T + bg ; LayerNorm ; dwconv ; silu --------
__global__ void __launch_bounds__(128) k_global_front(
    const float* __restrict__ f1, const float* __restrict__ f2,
    const float* __restrict__ Wg, const float* __restrict__ bg,
    const float* __restrict__ ln_g, const float* __restrict__ ln_b,
    const float* __restrict__ wcg, const float* __restrict__ bcg)
{
    const int TF = 48;
    __shared__ __align__(16) float sx[TF+3][64];
    __shared__ float red[8];
    int s = blockIdx.x;
    const float* f = ((s >> 1) ? f2 : f1) + (size_t)(s & 1) * 64 * LSEQ;
    int l0 = blockIdx.y * TF;
    int tid = threadIdx.x, lane = tid & 31, wid = tid >> 5;

    for (int idx = tid; idx < (TF+3)*64; idx += 128) {
        int c = idx & 63, j = idx >> 6;
        int gl = l0 - 1 + j;
        sx[j][c] = (gl >= 0 && gl < LSEQ) ? f[(size_t)c*LSEQ + gl] : 0.f;
    }
    __syncthreads();

    int c = tid;                              // channel 0..127
    float w[64];
    #pragma unroll 16
    for (int k = 0; k < 64; k++) w[k] = Wg[c*64 + k];
    float bias = bg[c], gam = ln_g[c], bet = ln_b[c];
    float cw0 = wcg[c*4], cw1 = wcg[c*4+1], cw2 = wcg[c*4+2], cw3 = wcg[c*4+3];
    float cb = bcg[c];
    float* outp = g_Ug + (size_t)s*LSEQ*128 + c;
    float x0 = 0.f, x1 = 0.f, x2 = 0.f;
    for (int j = 0; j < TF+3; j++) {
        int gl = l0 - 1 + j;
        float acc = bias;
        const float4* row = (const float4*)sx[j];
        #pragma unroll
        for (int k4 = 0; k4 < 16; k4++) {
            float4 v = row[k4];
            acc += v.x*w[4*k4] + v.y*w[4*k4+1] + v.z*w[4*k4+2] + v.w*w[4*k4+3];
        }
        // LayerNorm over the 128 channels (= 128 threads)
        float v1 = acc, v2 = acc*acc;
        #pragma unroll
        for (int o = 16; o; o >>= 1) {
            v1 += __shfl_xor_sync(0xffffffffu, v1, o);
            v2 += __shfl_xor_sync(0xffffffffu, v2, o);
        }
        if (lane == 0) { red[wid] = v1; red[4+wid] = v2; }
        __syncthreads();
        float S1 = red[0]+red[1]+red[2]+red[3];
        float S2 = red[4]+red[5]+red[6]+red[7];
        __syncthreads();
        float mu  = S1 * (1.f/128.f);
        float var = S2 * (1.f/128.f) - mu*mu;
        float xn = (acc - mu) * rsqrtf(var + 1e-5f) * gam + bet;
        if (gl < 0 || gl >= LSEQ) xn = 0.f;
        if (j >= 3) {
            float y = cw0*x0 + cw1*x1 + cw2*x2 + cw3*xn + cb;
            outp[(size_t)(l0 + j - 3) * 128] = siluf(y);
        }
        x0 = x1; x1 = x2; x2 = xn;
    }
}

// ---------------- projection: x_dbl -> (B,C) and delta ----------------------
template<int D>
__global__ void __launch_bounds__(128) k_proj(
    const float* __restrict__ Wxp, const float* __restrict__ Wdt,
    const float* __restrict__ bdt)
{
    const int T = 32;
    __shared__ float su[T][D];
    __shared__ float swx[36][D+1];
    __shared__ float sdt[T][4];
    const float* U   = (D == 64) ? g_Um : g_Ug;
    float*       BC  = (D == 64) ? g_BCm : g_BCg;
    float*       DEL = (D == 64) ? g_dm : g_dg;
    int s = blockIdx.x;
    int l0 = blockIdx.y * T;
    int tid = threadIdx.x;

    for (int i = tid; i < 36*D; i += 128) swx[i / D][i % D] = Wxp[i];
    const float* up = U + ((size_t)s*LSEQ + l0) * D;
    for (int i = tid; i < T*D; i += 128) su[i / D][i % D] = up[i];
    __syncthreads();

    for (int it = tid; it < T*36; it += 128) {
        int t = it / 36, r = it - t*36;
        const float* ur = su[t];
        const float* wr = swx[r];
        float acc = 0.f;
        #pragma unroll 8
        for (int k = 0; k < D; k++) acc += ur[k] * wr[k];
        if (r < 4) sdt[t][r] = acc;
        else       BC[((size_t)s*LSEQ + l0 + t)*32 + (r-4)] = acc;
    }
    __syncthreads();
    for (int it = tid; it < T*D; it += 128) {
        int d = it % D, t = it / D;
        float x = sdt[t][0]*Wdt[d*4]   + sdt[t][1]*Wdt[d*4+1]
                + sdt[t][2]*Wdt[d*4+2] + sdt[t][3]*Wdt[d*4+3] + bdt[d];
        DEL[((size_t)s*LSEQ + l0 + t)*D + d] = softplusf(x);
    }
}

// ---------------- scan phase A: per-chunk summaries --------------------------
template<int D>
__global__ void __launch_bounds__(D) k_scanA(const float* __restrict__ Alog)
{
    const float* DEL = (D == 64) ? g_dm  : g_dg;
    const float* U   = (D == 64) ? g_Um  : g_Ug;
    const float* BCp = (D == 64) ? g_BCm : g_BCg;
    float*       Sum = (D == 64) ? g_SumM : g_SumG;
    int s = blockIdx.x, ch = blockIdx.y;
    int d = threadIdx.x;
    float Ar[16];
    #pragma unroll
    for (int n = 0; n < 16; n++) Ar[n] = -__expf(Alog[d*16 + n]);
    float A0 = Ar[0];
    bool st = true;
    #pragma unroll
    for (int n = 1; n < 16; n++)
        if (fabsf(Ar[n] - (float)(n+1)*A0) > 1e-4f * fabsf(Ar[n])) st = false;

    float h[16];
    #pragma unroll
    for (int n = 0; n < 16; n++) h[n] = 0.f;
    float S = 0.f;
    size_t base = (size_t)s*LSEQ + (size_t)ch*TCH;
    const float* dp = DEL + base*D + d;
    const float* up = U   + base*D + d;
    const float4* bc = (const float4*)(BCp + base*32);
    for (int t = 0; t < TCH; t++) {
        float del = dp[(size_t)t*D];
        float u   = up[(size_t)t*D];
        float du  = del * u;
        float4 b0 = bc[t*8+0], b1 = bc[t*8+1], b2 = bc[t*8+2], b3 = bc[t*8+3];
        float a[16];
        if (st) powers16(__expf(del*A0), a);
        else {
            #pragma unroll
            for (int n = 0; n < 16; n++) a[n] = __expf(del*Ar[n]);
        }
        h[0]=a[0]*h[0]+du*b0.x;  h[1]=a[1]*h[1]+du*b0.y;
        h[2]=a[2]*h[2]+du*b0.z;  h[3]=a[3]*h[3]+du*b0.w;
        h[4]=a[4]*h[4]+du*b1.x;  h[5]=a[5]*h[5]+du*b1.y;
        h[6]=a[6]*h[6]+du*b1.z;  h[7]=a[7]*h[7]+du*b1.w;
        h[8]=a[8]*h[8]+du*b2.x;  h[9]=a[9]*h[9]+du*b2.y;
        h[10]=a[10]*h[10]+du*b2.z; h[11]=a[11]*h[11]+du*b2.w;
        h[12]=a[12]*h[12]+du*b3.x; h[13]=a[13]*h[13]+du*b3.y;
        h[14]=a[14]*h[14]+du*b3.z; h[15]=a[15]*h[15]+du*b3.w;
        S += del;
    }
    float ap[16];
    if (st) powers16(__expf(S*A0), ap);
    else {
        #pragma unroll
        for (int n = 0; n < 16; n++) ap[n] = __expf(S*Ar[n]);
    }
    float* o = Sum + (((size_t)s*NCHK + ch)*D + d)*32;
    #pragma unroll
    for (int n = 0; n < 16; n++) { o[n] = h[n]; o[16+n] = ap[n]; }
}

// ---------------- scan phase B: sequential prefix over chunks ----------------
__global__ void k_scanB(int D)
{
    const float* Sum = (D == 64) ? g_SumM : g_SumG;
    float*       Hin = (D == 64) ? g_HinM : g_HinG;
    int tid = blockIdx.x * 256 + threadIdx.x;
    if (tid >= 4*D*16) return;
    int n = tid & 15;
    int d = (tid >> 4) % D;
    int s = tid / (D*16);
    float hin = 0.f;
    for (int c = 0; c < NCHK; c++) {
        size_t i16 = (((size_t)s*NCHK + c)*D + d)*16 + n;
        size_t i32 = (((size_t)s*NCHK + c)*D + d)*32 + n;
        Hin[i16] = hin;
        hin = Sum[i32+16]*hin + Sum[i32];
    }
}

// ---------------- scan phase C: re-scan with carry, emit y -------------------
template<int D>
__global__ void __launch_bounds__(D) k_scanC(
    const float* __restrict__ Alog, const float* __restrict__ Dp)
{
    const float* DEL = (D == 64) ? g_dm  : g_dg;
    const float* U   = (D == 64) ? g_Um  : g_Ug;
    const float* BCp = (D == 64) ? g_BCm : g_BCg;
    const float* Hin = (D == 64) ? g_HinM : g_HinG;
    float*       Y   = (D == 64) ? g_ym  : g_yg;
    int s = blockIdx.x, ch = blockIdx.y;
    int d = threadIdx.x;
    float Ar[16];
    #pragma unroll
    for (int n = 0; n < 16; n++) Ar[n] = -__expf(Alog[d*16 + n]);
    float A0 = Ar[0];
    bool st = true;
    #pragma unroll
    for (int n = 1; n < 16; n++)
        if (fabsf(Ar[n] - (float)(n+1)*A0) > 1e-4f * fabsf(Ar[n])) st = false;

    float h[16];
    const float4* hp = (const float4*)(Hin + (((size_t)s*NCHK + ch)*D + d)*16);
    float4 h0 = hp[0], h1 = hp[1], h2 = hp[2], h3 = hp[3];
    h[0]=h0.x; h[1]=h0.y; h[2]=h0.z; h[3]=h0.w;
    h[4]=h1.x; h[5]=h1.y; h[6]=h1.z; h[7]=h1.w;
    h[8]=h2.x; h[9]=h2.y; h[10]=h2.z; h[11]=h2.w;
    h[12]=h3.x; h[13]=h3.y; h[14]=h3.z; h[15]=h3.w;
    float Dd = Dp[d];

    size_t base = (size_t)s*LSEQ + (size_t)ch*TCH;
    const float* dp = DEL + base*D + d;
    const float* up = U   + base*D + d;
    const float4* bc = (const float4*)(BCp + base*32);
    float* yp = Y + base*D + d;
    for (int t = 0; t < TCH; t++) {
        float del = dp[(size_t)t*D];
        float u   = up[(size_t)t*D];
        float du  = del * u;
        float4 b0 = bc[t*8+0], b1 = bc[t*8+1], b2 = bc[t*8+2], b3 = bc[t*8+3];
        float4 c0 = bc[t*8+4], c1 = bc[t*8+5], c2 = bc[t*8+6], c3 = bc[t*8+7];
        float a[16];
        if (st) powers16(__expf(del*A0), a);
        else {
            #pragma unroll
            for (int n = 0; n < 16; n++) a[n] = __expf(del*Ar[n]);
        }
        h[0]=a[0]*h[0]+du*b0.x;  h[1]=a[1]*h[1]+du*b0.y;
        h[2]=a[2]*h[2]+du*b0.z;  h[3]=a[3]*h[3]+du*b0.w;
        h[4]=a[4]*h[4]+du*b1.x;  h[5]=a[5]*h[5]+du*b1.y;
        h[6]=a[6]*h[6]+du*b1.z;  h[7]=a[7]*h[7]+du*b1.w;
        h[8]=a[8]*h[8]+du*b2.x;  h[9]=a[9]*h[9]+du*b2.y;
        h[10]=a[10]*h[10]+du*b2.z; h[11]=a[11]*h[11]+du*b2.w;
        h[12]=a[12]*h[12]+du*b3.x; h[13]=a[13]*h[13]+du*b3.y;
        h[14]=a[14]*h[14]+du*b3.z; h[15]=a[15]*h[15]+du*b3.w;
        float y = Dd*u;
        y += h[0]*c0.x + h[1]*c0.y + h[2]*c0.z + h[3]*c0.w;
        y += h[4]*c1.x + h[5]*c1.y + h[6]*c1.z + h[7]*c1.w;
        y += h[8]*c2.x + h[9]*c2.y + h[10]*c2.z + h[11]*c2.w;
        y += h[12]*c3.x + h[13]*c3.y + h[14]*c3.z + h[15]*c3.w;
        yp[(size_t)t*D] = y;
    }
}

// ---------------- output: o = (mixer ⊙ global) @ Wo^T + bo -------------------
__global__ void __launch_bounds__(256) k_out(
    const float* __restrict__ Wo, const float* __restrict__ bo,
    float* __restrict__ out)
{
    __shared__ __align__(16) float4 sp4[32][32];   // [token][k4], XOR-swizzled
    __shared__ float swo[32*128];                  // 32 Wo rows for this block
    int o = blockIdx.y >> 1, b = blockIdx.y & 1;
    int ch0 = blockIdx.z * 32;
    int l0 = blockIdx.x * 32;
    int tid = threadIdx.x;

    for (int i = tid; i < 32*128; i += 256) swo[i] = Wo[ch0*128 + i];

    int sm = (o == 0) ? b : 2 + b;     // mixer sequence
    int sg = (o == 0) ? 2 + b : b;     // global sequence
    const float* ym = g_ym + ((size_t)sm*LSEQ + l0)*64;
    const float* zz = g_Z  + ((size_t)sm*LSEQ + l0)*64;
    const float* yg = g_yg + ((size_t)sg*LSEQ + l0)*128;

    for (int i = tid; i < 32*128; i += 256) {
        int t = i >> 7, k = i & 127;
        float m = (k < 64) ? ym[t*64 + k] : zz[t*64 + (k-64)];
        float p = m * yg[t*128 + k];
        float* cell = (float*)&sp4[t][(k >> 2) ^ (t & 7)];
        cell[k & 3] = p;
    }
    __syncthreads();

    int w = tid >> 5, lane = tid & 31;  // warp w: 4 channels; lane = token
    float acc0 = bo[ch0 + w*4 + 0];
    float acc1 = bo[ch0 + w*4 + 1];
    float acc2 = bo[ch0 + w*4 + 2];
    float acc3 = bo[ch0 + w*4 + 3];
    const float4* w0 = (const float4*)(swo + (w*4+0)*128);
    const float4* w1 = (const float4*)(swo + (w*4+1)*128);
    const float4* w2 = (const float4*)(swo + (w*4+2)*128);
    const float4* w3 = (const float4*)(swo + (w*4+3)*128);
    #pragma unroll 8
    for (int k4 = 0; k4 < 32; k4++) {
        float4 p = sp4[lane][k4 ^ (lane & 7)];
        float4 v;
        v = w0[k4]; acc0 += p.x*v.x + p.y*v.y + p.z*v.z + p.w*v.w;
        v = w1[k4]; acc1 += p.x*v.x + p.y*v.y + p.z*v.z + p.w*v.w;
        v = w2[k4]; acc2 += p.x*v.x + p.y*v.y + p.z*v.z + p.w*v.w;
        v = w3[k4]; acc3 += p.x*v.x + p.y*v.y + p.z*v.z + p.w*v.w;
    }
    float* op = out + ((size_t)o*2 + b)*64*LSEQ + l0 + lane;
    op[(size_t)(ch0 + w*4 + 0)*LSEQ] = acc0;
    op[(size_t)(ch0 + w*4 + 1)*LSEQ] = acc1;
    op[(size_t)(ch0 + w*4 + 2)*LSEQ] = acc2;
    op[(size_t)(ch0 + w*4 + 3)*LSEQ] = acc3;
}

// -----------------------------------------------------------------------------
extern "C" void kernel_launch(void* const* d_in, const int* in_sizes, int n_in,
                              void* d_out, int out_size)
{
    const float* f1    = (const float*)d_in[0];
    const float* f2    = (const float*)d_in[1];
    const float* Wi    = (const float*)d_in[2];
    const float* bi    = (const float*)d_in[3];
    const float* wcx   = (const float*)d_in[4];
    const float* bcx   = (const float*)d_in[5];
    const float* wcz   = (const float*)d_in[6];
    const float* bcz   = (const float*)d_in[7];
    const float* Wxp_m = (const float*)d_in[8];
    const float* Wdt_m = (const float*)d_in[9];
    const float* bdt_m = (const float*)d_in[10];
    const float* Alog_m= (const float*)d_in[11];
    const float* Dm    = (const float*)d_in[12];
    const float* Wg    = (const float*)d_in[13];
    const float* bg    = (const float*)d_in[14];
    const float* ln_g  = (const float*)d_in[15];
    const float* ln_b  = (const float*)d_in[16];
    const float* wcg   = (const float*)d_in[17];
    const float* bcg   = (const float*)d_in[18];
    const float* Wxp_g = (const float*)d_in[19];
    const float* Wdt_g = (const float*)d_in[20];
    const float* bdt_g = (const float*)d_in[21];
    const float* Alog_g= (const float*)d_in[22];
    const float* Dg    = (const float*)d_in[23];
    const float* Wo    = (const float*)d_in[24];
    const float* bo    = (const float*)d_in[25];
    float* out = (float*)d_out;

    k_mixer_front <<<dim3(4, LSEQ/64), 128>>>(f1, f2, Wi, bi, wcx, bcx, wcz, bcz);
    k_global_front<<<dim3(4, LSEQ/48), 128>>>(f1, f2, Wg, bg, ln_g, ln_b, wcg, bcg);
    k_proj<64>   <<<dim3(4, LSEQ/32), 128>>>(Wxp_m, Wdt_m, bdt_m);
    k_proj<128>  <<<dim3(4, LSEQ/32), 128>>>(Wxp_g, Wdt_g, bdt_g);
    k_scanA<64>  <<<dim3(4, NCHK),  64>>>(Alog_m);
    k_scanA<128> <<<dim3(4, NCHK), 128>>>(Alog_g);
    k_scanB      <<<(4*64*16 + 255)/256, 256>>>(64);
    k_scanB      <<<(4*128*16 + 255)/256, 256>>>(128);
    k_scanC<64>  <<<dim3(4, NCHK),  64>>>(Alog_m, Dm);
    k_scanC<128> <<<dim3(4, NCHK), 128>>>(Alog_g, Dg);
    k_out        <<<dim3(LSEQ/32, 4, 2), 256>>>(Wo, bo, out);
}

// round 8
// speedup vs baseline: 1.0556x; 1.0556x over previous
#include <cuda_runtime.h>
#include <math.h>

#define LSEQ 9216
#define NCHK 288
#define TCH  32

// ------------------------- scratch (device globals) -------------------------
__device__ __align__(16) float g_Um [4*LSEQ*64];
__device__ __align__(16) float g_Z  [4*LSEQ*64];
__device__ __align__(16) float g_dm [4*LSEQ*64];
__device__ __align__(16) float g_BCm[4*LSEQ*32];
__device__ __align__(16) float g_ym [4*LSEQ*64];
__device__ __align__(16) float g_Ug [4*LSEQ*128];
__device__ __align__(16) float g_dg [4*LSEQ*128];
__device__ __align__(16) float g_BCg[4*LSEQ*32];
__device__ __align__(16) float g_yg [4*LSEQ*128];
__device__ __align__(16) float g_SumM[4*NCHK*64*32];
__device__ __align__(16) float g_SumG[4*NCHK*128*32];
__device__ __align__(16) float g_HinM[4*NCHK*64*16];
__device__ __align__(16) float g_HinG[4*NCHK*128*16];

__device__ __forceinline__ float siluf(float y) {
    return y / (1.f + __expf(-y));
}
__device__ __forceinline__ float softplusf(float x) {
    return (x > 20.f) ? x : log1pf(expf(x));
}
// pw[k] = e1^(k+1), k=0..15, log-depth multiply tree
__device__ __forceinline__ void powers16(float e1, float* pw) {
    pw[0]=e1;
    pw[1]=pw[0]*pw[0];  pw[2]=pw[1]*pw[0];  pw[3]=pw[1]*pw[1];
    pw[4]=pw[2]*pw[1];  pw[5]=pw[2]*pw[2];  pw[6]=pw[3]*pw[2];  pw[7]=pw[3]*pw[3];
    pw[8]=pw[4]*pw[3];  pw[9]=pw[4]*pw[4];  pw[10]=pw[5]*pw[4]; pw[11]=pw[5]*pw[5];
    pw[12]=pw[6]*pw[5]; pw[13]=pw[6]*pw[6]; pw[14]=pw[7]*pw[6]; pw[15]=pw[7]*pw[7];
}

// ======== mixer front: GEMM + dwconv + silu + FUSED proj/delta ==============
__global__ void __launch_bounds__(128) k_mixer_front(
    const float* __restrict__ f1, const float* __restrict__ f2,
    const float* __restrict__ Wi, const float* __restrict__ bi,
    const float* __restrict__ wcx, const float* __restrict__ bcx,
    const float* __restrict__ wcz, const float* __restrict__ bcz,
    const float* __restrict__ Wxp, const float* __restrict__ Wdt,
    const float* __restrict__ bdt)
{
    const int TF = 64;
    __shared__ __align__(16) float sx[TF+3][64];   // input tile (+halo)
    __shared__ __align__(16) float su[TF][68];     // conv+silu'd x half
    __shared__ __align__(16) float swx[36][68];    // Wxp rows
    __shared__ float sdt[TF][4];
    int s = blockIdx.x;
    const float* f = ((s >> 1) ? f2 : f1) + (size_t)(s & 1) * 64 * LSEQ;
    int l0 = blockIdx.y * TF;
    int tid = threadIdx.x;

    for (int idx = tid; idx < (TF+3)*64; idx += 128) {
        int c = idx & 63, j = idx >> 6;
        int gl = l0 - 1 + j;
        sx[j][c] = (gl >= 0 && gl < LSEQ) ? f[(size_t)c*LSEQ + gl] : 0.f;
    }
    for (int i = tid; i < 36*64; i += 128) swx[i >> 6][i & 63] = Wxp[i];
    __syncthreads();

    int c = tid;
    float w[64];
    #pragma unroll 16
    for (int k = 0; k < 64; k++) w[k] = Wi[c*64 + k];
    float bias = bi[c];
    const float* cw = (c < 64) ? (wcx + c*4) : (wcz + (c-64)*4);
    float cw0 = cw[0], cw1 = cw[1], cw2 = cw[2], cw3 = cw[3];
    float cb = (c < 64) ? bcx[c] : bcz[c-64];
    bool isx = (c < 64);
    float* outp = isx ? (g_Um + (size_t)s*LSEQ*64 + c)
                      : (g_Z  + (size_t)s*LSEQ*64 + (c-64));
    float x0 = 0.f, x1 = 0.f, x2 = 0.f;
    for (int j = 0; j < TF+3; j++) {
        int gl = l0 - 1 + j;
        float acc = bias;
        const float4* row = (const float4*)sx[j];
        #pragma unroll
        for (int k4 = 0; k4 < 16; k4++) {
            float4 v = row[k4];
            acc += v.x*w[4*k4] + v.y*w[4*k4+1] + v.z*w[4*k4+2] + v.w*w[4*k4+3];
        }
        if (gl < 0 || gl >= LSEQ) acc = 0.f;
        if (j >= 3) {
            float y = cw0*x0 + cw1*x1 + cw2*x2 + cw3*acc + cb;
            float v = siluf(y);
            outp[(size_t)(l0 + j - 3) * 64] = v;
            if (isx) su[j-3][c] = v;
        }
        x0 = x1; x1 = x2; x2 = acc;
    }
    __syncthreads();

    // ---- fused proj: x_dbl[t][r] = sum_k u[t][k]*Wxp[r][k] ----
    int q = tid & 3;
    #pragma unroll
    for (int p = 0; p < 2; p++) {
        int t = p*32 + (tid >> 2);
        float accr[9];
        #pragma unroll
        for (int j = 0; j < 9; j++) accr[j] = 0.f;
        const float4* u4 = (const float4*)su[t];
        #pragma unroll
        for (int k4 = 0; k4 < 16; k4++) {
            float4 uv = u4[k4];
            #pragma unroll
            for (int j = 0; j < 9; j++) {
                float4 wv = ((const float4*)swx[q*9 + j])[k4];
                accr[j] += uv.x*wv.x + uv.y*wv.y + uv.z*wv.z + uv.w*wv.w;
            }
        }
        #pragma unroll
        for (int j = 0; j < 9; j++) {
            int r = q*9 + j;
            if (r < 4) sdt[t][r] = accr[j];
            else g_BCm[((size_t)s*LSEQ + l0 + t)*32 + (r-4)] = accr[j];
        }
    }
    __syncthreads();

    // ---- delta ----
    for (int i = tid; i < TF*64; i += 128) {
        int t = i >> 6, d = i & 63;
        float x = sdt[t][0]*Wdt[d*4]   + sdt[t][1]*Wdt[d*4+1]
                + sdt[t][2]*Wdt[d*4+2] + sdt[t][3]*Wdt[d*4+3] + bdt[d];
        g_dm[((size_t)s*LSEQ + l0 + t)*64 + d] = softplusf(x);
    }
}

// ======== global front: GEMM + LN + dwconv + silu + FUSED proj/delta ========
__global__ void __launch_bounds__(128) k_global_front(
    const float* __restrict__ f1, const float* __restrict__ f2,
    const float* __restrict__ Wg, const float* __restrict__ bg,
    const float* __restrict__ ln_g, const float* __restrict__ ln_b,
    const float* __restrict__ wcg, const float* __restrict__ bcg,
    const float* __restrict__ Wxp, const float* __restrict__ Wdt,
    const float* __restrict__ bdt)
{
    const int TF = 32;
    __shared__ __align__(16) float sx[TF+3][64];    // 8960 B
    __shared__ __align__(16) float sh[TF+3][132];   // raw h -> LN'd -> u rows 0..31
    __shared__ __align__(16) float swx[36][132];    // 19008 B
    __shared__ float sdt[TF][4];
    int s = blockIdx.x;
    const float* f = ((s >> 1) ? f2 : f1) + (size_t)(s & 1) * 64 * LSEQ;
    int l0 = blockIdx.y * TF;
    int tid = threadIdx.x, lane = tid & 31, wid = tid >> 5;

    for (int idx = tid; idx < (TF+3)*64; idx += 128) {
        int c = idx & 63, j = idx >> 6;
        int gl = l0 - 1 + j;
        sx[j][c] = (gl >= 0 && gl < LSEQ) ? f[(size_t)c*LSEQ + gl] : 0.f;
    }
    for (int i = tid; i < 36*128; i += 128) swx[i >> 7][i & 127] = Wxp[i];
    __syncthreads();

    int c = tid;
    {
        float w[64];
        #pragma unroll 16
        for (int k = 0; k < 64; k++) w[k] = Wg[c*64 + k];
        float bias = bg[c];
        for (int j = 0; j < TF+3; j++) {
            float acc = bias;
            const float4* row = (const float4*)sx[j];
            #pragma unroll
            for (int k4 = 0; k4 < 16; k4++) {
                float4 v = row[k4];
                acc += v.x*w[4*k4] + v.y*w[4*k4+1] + v.z*w[4*k4+2] + v.w*w[4*k4+3];
            }
            sh[j][c] = acc;
        }
    }
    __syncthreads();

    // ---- LayerNorm, one warp per token, warp-local reduction ----
    {
        float g0 = ln_g[lane],    g1 = ln_g[lane+32], g2 = ln_g[lane+64], g3 = ln_g[lane+96];
        float b0 = ln_b[lane],    b1 = ln_b[lane+32], b2 = ln_b[lane+64], b3 = ln_b[lane+96];
        for (int t = wid; t < TF+3; t += 4) {
            float a0 = sh[t][lane], a1 = sh[t][lane+32], a2 = sh[t][lane+64], a3 = sh[t][lane+96];
            float s1 = a0+a1+a2+a3;
            float s2 = a0*a0+a1*a1+a2*a2+a3*a3;
            #pragma unroll
            for (int o = 16; o; o >>= 1) {
                s1 += __shfl_xor_sync(0xffffffffu, s1, o);
                s2 += __shfl_xor_sync(0xffffffffu, s2, o);
            }
            float mu = s1 * (1.f/128.f);
            float rs = rsqrtf(s2 * (1.f/128.f) - mu*mu + 1e-5f);
            sh[t][lane]    = (a0-mu)*rs*g0 + b0;
            sh[t][lane+32] = (a1-mu)*rs*g1 + b1;
            sh[t][lane+64] = (a2-mu)*rs*g2 + b2;
            sh[t][lane+96] = (a3-mu)*rs*g3 + b3;
        }
    }
    __syncthreads();

    // ---- dwconv + silu; store u to gmem and recycle sh rows 0..TF-1 for u ----
    {
        float cw0 = wcg[c*4], cw1 = wcg[c*4+1], cw2 = wcg[c*4+2], cw3 = wcg[c*4+3];
        float cb = bcg[c];
        float* outp = g_Ug + (size_t)s*LSEQ*128 + c;
        float x0 = 0.f, x1 = 0.f, x2 = 0.f;
        for (int j = 0; j < TF+3; j++) {
            int gl = l0 - 1 + j;
            float xn = (gl >= 0 && gl < LSEQ) ? sh[j][c] : 0.f;
            if (j >= 3) {
                float y = cw0*x0 + cw1*x1 + cw2*x2 + cw3*xn + cb;
                float v = siluf(y);
                outp[(size_t)(l0 + j - 3) * 128] = v;
                sh[j-3][c] = v;      // own column only; safe pre-bar
            }
            x0 = x1; x1 = x2; x2 = xn;
        }
    }
    __syncthreads();

    // ---- fused proj ----
    {
        int t = tid >> 2, q = tid & 3;
        float accr[9];
        #pragma unroll
        for (int j = 0; j < 9; j++) accr[j] = 0.f;
        const float4* u4 = (const float4*)sh[t];
        #pragma unroll
        for (int k4 = 0; k4 < 32; k4++) {
            float4 uv = u4[k4];
            #pragma unroll
            for (int j = 0; j < 9; j++) {
                float4 wv = ((const float4*)swx[q*9 + j])[k4];
                accr[j] += uv.x*wv.x + uv.y*wv.y + uv.z*wv.z + uv.w*wv.w;
            }
        }
        #pragma unroll
        for (int j = 0; j < 9; j++) {
            int r = q*9 + j;
            if (r < 4) sdt[t][r] = accr[j];
            else g_BCg[((size_t)s*LSEQ + l0 + t)*32 + (r-4)] = accr[j];
        }
    }
    __syncthreads();

    // ---- delta ----
    for (int i = tid; i < TF*128; i += 128) {
        int t = i >> 7, d = i & 127;
        float x = sdt[t][0]*Wdt[d*4]   + sdt[t][1]*Wdt[d*4+1]
                + sdt[t][2]*Wdt[d*4+2] + sdt[t][3]*Wdt[d*4+3] + bdt[d];
        g_dg[((size_t)s*LSEQ + l0 + t)*128 + d] = softplusf(x);
    }
}

// ---------------- scan phase A: per-chunk summaries --------------------------
template<int D>
__global__ void __launch_bounds__(D) k_scanA(const float* __restrict__ Alog)
{
    const float* DEL = (D == 64) ? g_dm  : g_dg;
    const float* U   = (D == 64) ? g_Um  : g_Ug;
    const float* BCp = (D == 64) ? g_BCm : g_BCg;
    float*       Sum = (D == 64) ? g_SumM : g_SumG;
    int s = blockIdx.x, ch = blockIdx.y;
    int d = threadIdx.x;
    float Ar[16];
    #pragma unroll
    for (int n = 0; n < 16; n++) Ar[n] = -__expf(Alog[d*16 + n]);
    float A0 = Ar[0];
    bool st = true;
    #pragma unroll
    for (int n = 1; n < 16; n++)
        if (fabsf(Ar[n] - (float)(n+1)*A0) > 1e-4f * fabsf(Ar[n])) st = false;

    float h[16];
    #pragma unroll
    for (int n = 0; n < 16; n++) h[n] = 0.f;
    float S = 0.f;
    size_t base = (size_t)s*LSEQ + (size_t)ch*TCH;
    const float* dp = DEL + base*D + d;
    const float* up = U   + base*D + d;
    const float4* bc = (const float4*)(BCp + base*32);
    #pragma unroll 4
    for (int t = 0; t < TCH; t++) {
        float del = dp[(size_t)t*D];
        float u   = up[(size_t)t*D];
        float du  = del * u;
        float4 b0 = bc[t*8+0], b1 = bc[t*8+1], b2 = bc[t*8+2], b3 = bc[t*8+3];
        float a[16];
        if (st) powers16(__expf(del*A0), a);
        else {
            #pragma unroll
            for (int n = 0; n < 16; n++) a[n] = __expf(del*Ar[n]);
        }
        h[0]=a[0]*h[0]+du*b0.x;  h[1]=a[1]*h[1]+du*b0.y;
        h[2]=a[2]*h[2]+du*b0.z;  h[3]=a[3]*h[3]+du*b0.w;
        h[4]=a[4]*h[4]+du*b1.x;  h[5]=a[5]*h[5]+du*b1.y;
        h[6]=a[6]*h[6]+du*b1.z;  h[7]=a[7]*h[7]+du*b1.w;
        h[8]=a[8]*h[8]+du*b2.x;  h[9]=a[9]*h[9]+du*b2.y;
        h[10]=a[10]*h[10]+du*b2.z; h[11]=a[11]*h[11]+du*b2.w;
        h[12]=a[12]*h[12]+du*b3.x; h[13]=a[13]*h[13]+du*b3.y;
        h[14]=a[14]*h[14]+du*b3.z; h[15]=a[15]*h[15]+du*b3.w;
        S += del;
    }
    float ap[16];
    if (st) powers16(__expf(S*A0), ap);
    else {
        #pragma unroll
        for (int n = 0; n < 16; n++) ap[n] = __expf(S*Ar[n]);
    }
    float* o = Sum + (((size_t)s*NCHK + ch)*D + d)*32;
    #pragma unroll
    for (int n = 0; n < 16; n++) { o[n] = h[n]; o[16+n] = ap[n]; }
}

// ---------------- scan phase B: sequential prefix over chunks (both D) ------
__global__ void k_scanB()
{
    int tid = blockIdx.x * 256 + threadIdx.x;
    const float* Sum; float* Hin; int D;
    if (tid < 4*64*16) { Sum = g_SumM; Hin = g_HinM; D = 64; }
    else {
        tid -= 4*64*16;
        if (tid >= 4*128*16) return;
        Sum = g_SumG; Hin = g_HinG; D = 128;
    }
    int n = tid & 15;
    int d = (tid >> 4) % D;
    int s = tid / (D*16);
    float hin = 0.f;
    #pragma unroll 4
    for (int c = 0; c < NCHK; c++) {
        size_t i16 = (((size_t)s*NCHK + c)*D + d)*16 + n;
        size_t i32 = (((size_t)s*NCHK + c)*D + d)*32 + n;
        Hin[i16] = hin;
        hin = Sum[i32+16]*hin + Sum[i32];
    }
}

// ---------------- scan phase C: re-scan with carry, emit y -------------------
template<int D>
__global__ void __launch_bounds__(D) k_scanC(
    const float* __restrict__ Alog, const float* __restrict__ Dp)
{
    const float* DEL = (D == 64) ? g_dm  : g_dg;
    const float* U   = (D == 64) ? g_Um  : g_Ug;
    const float* BCp = (D == 64) ? g_BCm : g_BCg;
    const float* Hin = (D == 64) ? g_HinM : g_HinG;
    float*       Y   = (D == 64) ? g_ym  : g_yg;
    int s = blockIdx.x, ch = blockIdx.y;
    int d = threadIdx.x;
    float Ar[16];
    #pragma unroll
    for (int n = 0; n < 16; n++) Ar[n] = -__expf(Alog[d*16 + n]);
    float A0 = Ar[0];
    bool st = true;
    #pragma unroll
    for (int n = 1; n < 16; n++)
        if (fabsf(Ar[n] - (float)(n+1)*A0) > 1e-4f * fabsf(Ar[n])) st = false;

    float h[16];
    const float4* hp = (const float4*)(Hin + (((size_t)s*NCHK + ch)*D + d)*16);
    float4 h0 = hp[0], h1 = hp[1], h2 = hp[2], h3 = hp[3];
    h[0]=h0.x; h[1]=h0.y; h[2]=h0.z; h[3]=h0.w;
    h[4]=h1.x; h[5]=h1.y; h[6]=h1.z; h[7]=h1.w;
    h[8]=h2.x; h[9]=h2.y; h[10]=h2.z; h[11]=h2.w;
    h[12]=h3.x; h[13]=h3.y; h[14]=h3.z; h[15]=h3.w;
    float Dd = Dp[d];

    size_t base = (size_t)s*LSEQ + (size_t)ch*TCH;
    const float* dp = DEL + base*D + d;
    const float* up = U   + base*D + d;
    const float4* bc = (const float4*)(BCp + base*32);
    float* yp = Y + base*D + d;
    #pragma unroll 4
    for (int t = 0; t < TCH; t++) {
        float del = dp[(size_t)t*D];
        float u   = up[(size_t)t*D];
        float du  = del * u;
        float4 b0 = bc[t*8+0], b1 = bc[t*8+1], b2 = bc[t*8+2], b3 = bc[t*8+3];
        float4 c0 = bc[t*8+4], c1 = bc[t*8+5], c2 = bc[t*8+6], c3 = bc[t*8+7];
        float a[16];
        if (st) powers16(__expf(del*A0), a);
        else {
            #pragma unroll
            for (int n = 0; n < 16; n++) a[n] = __expf(del*Ar[n]);
        }
        h[0]=a[0]*h[0]+du*b0.x;  h[1]=a[1]*h[1]+du*b0.y;
        h[2]=a[2]*h[2]+du*b0.z;  h[3]=a[3]*h[3]+du*b0.w;
        h[4]=a[4]*h[4]+du*b1.x;  h[5]=a[5]*h[5]+du*b1.y;
        h[6]=a[6]*h[6]+du*b1.z;  h[7]=a[7]*h[7]+du*b1.w;
        h[8]=a[8]*h[8]+du*b2.x;  h[9]=a[9]*h[9]+du*b2.y;
        h[10]=a[10]*h[10]+du*b2.z; h[11]=a[11]*h[11]+du*b2.w;
        h[12]=a[12]*h[12]+du*b3.x; h[13]=a[13]*h[13]+du*b3.y;
        h[14]=a[14]*h[14]+du*b3.z; h[15]=a[15]*h[15]+du*b3.w;
        float y = Dd*u;
        y += h[0]*c0.x + h[1]*c0.y + h[2]*c0.z + h[3]*c0.w;
        y += h[4]*c1.x + h[5]*c1.y + h[6]*c1.z + h[7]*c1.w;
        y += h[8]*c2.x + h[9]*c2.y + h[10]*c2.z + h[11]*c2.w;
        y += h[12]*c3.x + h[13]*c3.y + h[14]*c3.z + h[15]*c3.w;
        yp[(size_t)t*D] = y;
    }
}

// ---------------- output: o = (mixer ⊙ global) @ Wo^T + bo -------------------
// tile: 64 tokens x 64 channels, thread = 4 tok x 4 ch register tile
__global__ void __launch_bounds__(256) k_out(
    const float* __restrict__ Wo, const float* __restrict__ bo,
    float* __restrict__ out)
{
    __shared__ __align__(16) float sp[64*132];   // p = m*g, row pad 132
    int o = blockIdx.y >> 1, b = blockIdx.y & 1;
    int l0 = blockIdx.x * 64;
    int tid = threadIdx.x;

    int sm = (o == 0) ? b : 2 + b;
    int sg = (o == 0) ? 2 + b : b;
    const float* ym = g_ym + ((size_t)sm*LSEQ + l0)*64;
    const float* zz = g_Z  + ((size_t)sm*LSEQ + l0)*64;
    const float* yg = g_yg + ((size_t)sg*LSEQ + l0)*128;

    for (int i = tid; i < 64*128; i += 256) {
        int t = i >> 7, k = i & 127;
        float m = (k < 64) ? ym[t*64 + k] : zz[t*64 + (k-64)];
        sp[t*132 + k] = m * yg[t*128 + k];
    }
    __syncthreads();

    int tx = tid & 15, ty = tid >> 4;      // ch group, token group
    int ch0 = tx * 4, t0 = ty * 4;
    float acc[4][4];
    #pragma unroll
    for (int i = 0; i < 4; i++)
        #pragma unroll
        for (int j = 0; j < 4; j++) acc[i][j] = 0.f;

    const float4* p0 = (const float4*)(sp + (t0+0)*132);
    const float4* p1 = (const float4*)(sp + (t0+1)*132);
    const float4* p2 = (const float4*)(sp + (t0+2)*132);
    const float4* p3 = (const float4*)(sp + (t0+3)*132);
    const float4* w0 = (const float4*)(Wo + (ch0+0)*128);
    const float4* w1 = (const float4*)(Wo + (ch0+1)*128);
    const float4* w2 = (const float4*)(Wo + (ch0+2)*128);
    const float4* w3 = (const float4*)(Wo + (ch0+3)*128);
    #pragma unroll 8
    for (int k4 = 0; k4 < 32; k4++) {
        float4 pv[4] = { p0[k4], p1[k4], p2[k4], p3[k4] };
        float4 wv[4] = { __ldg(w0+k4), __ldg(w1+k4), __ldg(w2+k4), __ldg(w3+k4) };
        #pragma unroll
        for (int i = 0; i < 4; i++)
            #pragma unroll
            for (int j = 0; j < 4; j++)
                acc[i][j] += pv[i].x*wv[j].x + pv[i].y*wv[j].y
                           + pv[i].z*wv[j].z + pv[i].w*wv[j].w;
    }
    float* op = out + ((size_t)o*2 + b)*64*LSEQ;
    #pragma unroll
    for (int j = 0; j < 4; j++) {
        float bj = bo[ch0 + j];
        float4 v = { acc[0][j]+bj, acc[1][j]+bj, acc[2][j]+bj, acc[3][j]+bj };
        *(float4*)(op + (size_t)(ch0+j)*LSEQ + l0 + t0) = v;
    }
}

// -----------------------------------------------------------------------------
extern "C" void kernel_launch(void* const* d_in, const int* in_sizes, int n_in,
                              void* d_out, int out_size)
{
    const float* f1    = (const float*)d_in[0];
    const float* f2    = (const float*)d_in[1];
    const float* Wi    = (const float*)d_in[2];
    const float* bi    = (const float*)d_in[3];
    const float* wcx   = (const float*)d_in[4];
    const float* bcx   = (const float*)d_in[5];
    const float* wcz   = (const float*)d_in[6];
    const float* bcz   = (const float*)d_in[7];
    const float* Wxp_m = (const float*)d_in[8];
    const float* Wdt_m = (const float*)d_in[9];
    const float* bdt_m = (const float*)d_in[10];
    const float* Alog_m= (const float*)d_in[11];
    const float* Dm    = (const float*)d_in[12];
    const float* Wg    = (const float*)d_in[13];
    const float* bg    = (const float*)d_in[14];
    const float* ln_g  = (const float*)d_in[15];
    const float* ln_b  = (const float*)d_in[16];
    const float* wcg   = (const float*)d_in[17];
    const float* bcg   = (const float*)d_in[18];
    const float* Wxp_g = (const float*)d_in[19];
    const float* Wdt_g = (const float*)d_in[20];
    const float* bdt_g = (const float*)d_in[21];
    const float* Alog_g= (const float*)d_in[22];
    const float* Dg    = (const float*)d_in[23];
    const float* Wo    = (const float*)d_in[24];
    const float* bo    = (const float*)d_in[25];
    float* out = (float*)d_out;

    k_mixer_front <<<dim3(4, LSEQ/64), 128>>>(f1, f2, Wi, bi, wcx, bcx, wcz, bcz,
                                              Wxp_m, Wdt_m, bdt_m);
    k_global_front<<<dim3(4, LSEQ/32), 128>>>(f1, f2, Wg, bg, ln_g, ln_b, wcg, bcg,
                                              Wxp_g, Wdt_g, bdt_g);
    k_scanA<64>  <<<dim3(4, NCHK),  64>>>(Alog_m);
    k_scanA<128> <<<dim3(4, NCHK), 128>>>(Alog_g);
    k_scanB      <<<(4*64*16 + 4*128*16 + 255)/256, 256>>>();
    k_scanC<64>  <<<dim3(4, NCHK),  64>>>(Alog_m, Dm);
    k_scanC<128> <<<dim3(4, NCHK), 128>>>(Alog_g, Dg);
    k_out        <<<dim3(LSEQ/64, 4), 256>>>(Wo, bo, out);
}

// round 9
// speedup vs baseline: 1.1825x; 1.1203x over previous
#include <cuda_runtime.h>
#include <math.h>

#define LSEQ 9216
#define NCHK 288
#define TCH  32

// ------------------------- scratch (device globals) -------------------------
__device__ __align__(16) float g_Um [4*LSEQ*64];
__device__ __align__(16) float g_Z  [4*LSEQ*64];
__device__ __align__(16) float g_dm [4*LSEQ*64];
__device__ __align__(16) float g_BCm[4*LSEQ*32];
__device__ __align__(16) float g_ym [4*LSEQ*64];
__device__ __align__(16) float g_Ug [4*LSEQ*128];
__device__ __align__(16) float g_dg [4*LSEQ*128];
__device__ __align__(16) float g_BCg[4*LSEQ*32];
__device__ __align__(16) float g_yg [4*LSEQ*128];
__device__ __align__(16) float g_SumM[4*NCHK*64*32];
__device__ __align__(16) float g_SumG[4*NCHK*128*32];
__device__ __align__(16) float g_HinM[4*NCHK*64*16];
__device__ __align__(16) float g_HinG[4*NCHK*128*16];

__device__ __forceinline__ float siluf(float y) {
    return y / (1.f + __expf(-y));
}
__device__ __forceinline__ float softplusf(float x) {
    return (x > 20.f) ? x : log1pf(expf(x));
}
// pw[k] = e1^(k+1), k=0..15, log-depth multiply tree
__device__ __forceinline__ void powers16(float e1, float* pw) {
    pw[0]=e1;
    pw[1]=pw[0]*pw[0];  pw[2]=pw[1]*pw[0];  pw[3]=pw[1]*pw[1];
    pw[4]=pw[2]*pw[1];  pw[5]=pw[2]*pw[2];  pw[6]=pw[3]*pw[2];  pw[7]=pw[3]*pw[3];
    pw[8]=pw[4]*pw[3];  pw[9]=pw[4]*pw[4];  pw[10]=pw[5]*pw[4]; pw[11]=pw[5]*pw[5];
    pw[12]=pw[6]*pw[5]; pw[13]=pw[6]*pw[6]; pw[14]=pw[7]*pw[6]; pw[15]=pw[7]*pw[7];
}

// ======== mixer front: GEMM + dwconv + silu + FUSED proj/delta ==============
__global__ void __launch_bounds__(128) k_mixer_front(
    const float* __restrict__ f1, const float* __restrict__ f2,
    const float* __restrict__ Wi, const float* __restrict__ bi,
    const float* __restrict__ wcx, const float* __restrict__ bcx,
    const float* __restrict__ wcz, const float* __restrict__ bcz,
    const float* __restrict__ Wxp, const float* __restrict__ Wdt,
    const float* __restrict__ bdt)
{
    const int TF = 64;
    __shared__ __align__(16) float sx[TF+3][64];
    __shared__ __align__(16) float su[TF][68];
    __shared__ __align__(16) float swx[36][68];
    __shared__ float sdt[TF][4];
    int s = blockIdx.x;
    const float* f = ((s >> 1) ? f2 : f1) + (size_t)(s & 1) * 64 * LSEQ;
    int l0 = blockIdx.y * TF;
    int tid = threadIdx.x;

    for (int idx = tid; idx < (TF+3)*64; idx += 128) {
        int c = idx & 63, j = idx >> 6;
        int gl = l0 - 1 + j;
        sx[j][c] = (gl >= 0 && gl < LSEQ) ? f[(size_t)c*LSEQ + gl] : 0.f;
    }
    for (int i = tid; i < 36*64; i += 128) swx[i >> 6][i & 63] = Wxp[i];
    __syncthreads();

    int c = tid;
    float w[64];
    #pragma unroll 16
    for (int k = 0; k < 64; k++) w[k] = Wi[c*64 + k];
    float bias = bi[c];
    const float* cw = (c < 64) ? (wcx + c*4) : (wcz + (c-64)*4);
    float cw0 = cw[0], cw1 = cw[1], cw2 = cw[2], cw3 = cw[3];
    float cb = (c < 64) ? bcx[c] : bcz[c-64];
    bool isx = (c < 64);
    float* outp = isx ? (g_Um + (size_t)s*LSEQ*64 + c)
                      : (g_Z  + (size_t)s*LSEQ*64 + (c-64));
    float x0 = 0.f, x1 = 0.f, x2 = 0.f;
    for (int j = 0; j < TF+3; j++) {
        int gl = l0 - 1 + j;
        float acc = bias;
        const float4* row = (const float4*)sx[j];
        #pragma unroll
        for (int k4 = 0; k4 < 16; k4++) {
            float4 v = row[k4];
            acc += v.x*w[4*k4] + v.y*w[4*k4+1] + v.z*w[4*k4+2] + v.w*w[4*k4+3];
        }
        if (gl < 0 || gl >= LSEQ) acc = 0.f;
        if (j >= 3) {
            float y = cw0*x0 + cw1*x1 + cw2*x2 + cw3*acc + cb;
            float v = siluf(y);
            outp[(size_t)(l0 + j - 3) * 64] = v;
            if (isx) su[j-3][c] = v;
        }
        x0 = x1; x1 = x2; x2 = acc;
    }
    __syncthreads();

    // ---- fused proj ----
    int q = tid & 3;
    #pragma unroll
    for (int p = 0; p < 2; p++) {
        int t = p*32 + (tid >> 2);
        float accr[9];
        #pragma unroll
        for (int j = 0; j < 9; j++) accr[j] = 0.f;
        const float4* u4 = (const float4*)su[t];
        #pragma unroll
        for (int k4 = 0; k4 < 16; k4++) {
            float4 uv = u4[k4];
            #pragma unroll
            for (int j = 0; j < 9; j++) {
                float4 wv = ((const float4*)swx[q*9 + j])[k4];
                accr[j] += uv.x*wv.x + uv.y*wv.y + uv.z*wv.z + uv.w*wv.w;
            }
        }
        #pragma unroll
        for (int j = 0; j < 9; j++) {
            int r = q*9 + j;
            if (r < 4) sdt[t][r] = accr[j];
            else g_BCm[((size_t)s*LSEQ + l0 + t)*32 + (r-4)] = accr[j];
        }
    }
    __syncthreads();

    // ---- delta ----
    for (int i = tid; i < TF*64; i += 128) {
        int t = i >> 6, d = i & 63;
        float x = sdt[t][0]*Wdt[d*4]   + sdt[t][1]*Wdt[d*4+1]
                + sdt[t][2]*Wdt[d*4+2] + sdt[t][3]*Wdt[d*4+3] + bdt[d];
        g_dm[((size_t)s*LSEQ + l0 + t)*64 + d] = softplusf(x);
    }
}

// ======== global front: GEMM + LN + dwconv + silu + FUSED proj/delta ========
__global__ void __launch_bounds__(128) k_global_front(
    const float* __restrict__ f1, const float* __restrict__ f2,
    const float* __restrict__ Wg, const float* __restrict__ bg,
    const float* __restrict__ ln_g, const float* __restrict__ ln_b,
    const float* __restrict__ wcg, const float* __restrict__ bcg,
    const float* __restrict__ Wxp, const float* __restrict__ Wdt,
    const float* __restrict__ bdt)
{
    const int TF = 32;
    __shared__ __align__(16) float sx[TF+3][64];
    __shared__ __align__(16) float sh[TF+3][132];
    __shared__ __align__(16) float swx[36][132];
    __shared__ float sdt[TF][4];
    int s = blockIdx.x;
    const float* f = ((s >> 1) ? f2 : f1) + (size_t)(s & 1) * 64 * LSEQ;
    int l0 = blockIdx.y * TF;
    int tid = threadIdx.x, lane = tid & 31, wid = tid >> 5;

    for (int idx = tid; idx < (TF+3)*64; idx += 128) {
        int c = idx & 63, j = idx >> 6;
        int gl = l0 - 1 + j;
        sx[j][c] = (gl >= 0 && gl < LSEQ) ? f[(size_t)c*LSEQ + gl] : 0.f;
    }
    for (int i = tid; i < 36*128; i += 128) swx[i >> 7][i & 127] = Wxp[i];
    __syncthreads();

    int c = tid;
    {
        float w[64];
        #pragma unroll 16
        for (int k = 0; k < 64; k++) w[k] = Wg[c*64 + k];
        float bias = bg[c];
        for (int j = 0; j < TF+3; j++) {
            float acc = bias;
            const float4* row = (const float4*)sx[j];
            #pragma unroll
            for (int k4 = 0; k4 < 16; k4++) {
                float4 v = row[k4];
                acc += v.x*w[4*k4] + v.y*w[4*k4+1] + v.z*w[4*k4+2] + v.w*w[4*k4+3];
            }
            sh[j][c] = acc;
        }
    }
    __syncthreads();

    {
        float g0 = ln_g[lane],    g1 = ln_g[lane+32], g2 = ln_g[lane+64], g3 = ln_g[lane+96];
        float b0 = ln_b[lane],    b1 = ln_b[lane+32], b2 = ln_b[lane+64], b3 = ln_b[lane+96];
        for (int t = wid; t < TF+3; t += 4) {
            float a0 = sh[t][lane], a1 = sh[t][lane+32], a2 = sh[t][lane+64], a3 = sh[t][lane+96];
            float s1 = a0+a1+a2+a3;
            float s2 = a0*a0+a1*a1+a2*a2+a3*a3;
            #pragma unroll
            for (int o = 16; o; o >>= 1) {
                s1 += __shfl_xor_sync(0xffffffffu, s1, o);
                s2 += __shfl_xor_sync(0xffffffffu, s2, o);
            }
            float mu = s1 * (1.f/128.f);
            float rs = rsqrtf(s2 * (1.f/128.f) - mu*mu + 1e-5f);
            sh[t][lane]    = (a0-mu)*rs*g0 + b0;
            sh[t][lane+32] = (a1-mu)*rs*g1 + b1;
            sh[t][lane+64] = (a2-mu)*rs*g2 + b2;
            sh[t][lane+96] = (a3-mu)*rs*g3 + b3;
        }
    }
    __syncthreads();

    {
        float cw0 = wcg[c*4], cw1 = wcg[c*4+1], cw2 = wcg[c*4+2], cw3 = wcg[c*4+3];
        float cb = bcg[c];
        float* outp = g_Ug + (size_t)s*LSEQ*128 + c;
        float x0 = 0.f, x1 = 0.f, x2 = 0.f;
        for (int j = 0; j < TF+3; j++) {
            int gl = l0 - 1 + j;
            float xn = (gl >= 0 && gl < LSEQ) ? sh[j][c] : 0.f;
            if (j >= 3) {
                float y = cw0*x0 + cw1*x1 + cw2*x2 + cw3*xn + cb;
                float v = siluf(y);
                outp[(size_t)(l0 + j - 3) * 128] = v;
                sh[j-3][c] = v;
            }
            x0 = x1; x1 = x2; x2 = xn;
        }
    }
    __syncthreads();

    {
        int t = tid >> 2, q = tid & 3;
        float accr[9];
        #pragma unroll
        for (int j = 0; j < 9; j++) accr[j] = 0.f;
        const float4* u4 = (const float4*)sh[t];
        #pragma unroll
        for (int k4 = 0; k4 < 32; k4++) {
            float4 uv = u4[k4];
            #pragma unroll
            for (int j = 0; j < 9; j++) {
                float4 wv = ((const float4*)swx[q*9 + j])[k4];
                accr[j] += uv.x*wv.x + uv.y*wv.y + uv.z*wv.z + uv.w*wv.w;
            }
        }
        #pragma unroll
        for (int j = 0; j < 9; j++) {
            int r = q*9 + j;
            if (r < 4) sdt[t][r] = accr[j];
            else g_BCg[((size_t)s*LSEQ + l0 + t)*32 + (r-4)] = accr[j];
        }
    }
    __syncthreads();

    for (int i = tid; i < TF*128; i += 128) {
        int t = i >> 7, d = i & 127;
        float x = sdt[t][0]*Wdt[d*4]   + sdt[t][1]*Wdt[d*4+1]
                + sdt[t][2]*Wdt[d*4+2] + sdt[t][3]*Wdt[d*4+3] + bdt[d];
        g_dg[((size_t)s*LSEQ + l0 + t)*128 + d] = softplusf(x);
    }
}

// ---------------- scan phase A: per-chunk summaries (smem-staged) -----------
template<int D>
__global__ void __launch_bounds__(D) k_scanA(const float* __restrict__ Alog)
{
    __shared__ __align__(16) float s_del[TCH*D];
    __shared__ __align__(16) float s_u  [TCH*D];
    __shared__ __align__(16) float s_bc [TCH*32];
    const float* DEL = (D == 64) ? g_dm  : g_dg;
    const float* U   = (D == 64) ? g_Um  : g_Ug;
    const float* BCp = (D == 64) ? g_BCm : g_BCg;
    float*       Sum = (D == 64) ? g_SumM : g_SumG;
    int s = blockIdx.x, ch = blockIdx.y;
    int d = threadIdx.x;
    size_t base = (size_t)s*LSEQ + (size_t)ch*TCH;

    {   // coalesced bulk stage (independent LDG.128s -> high MLP)
        const float4* gdel = (const float4*)(DEL + base*D);
        const float4* gu   = (const float4*)(U   + base*D);
        const float4* gbc  = (const float4*)(BCp + base*32);
        float4* sdel = (float4*)s_del;
        float4* sun  = (float4*)s_u;
        float4* sbc  = (float4*)s_bc;
        #pragma unroll
        for (int i = 0; i < TCH*D/4/D; i++) { int k = i*D + d; sdel[k] = gdel[k]; }
        #pragma unroll
        for (int i = 0; i < TCH*D/4/D; i++) { int k = i*D + d; sun[k] = gu[k]; }
        for (int k = d; k < TCH*8; k += D) sbc[k] = gbc[k];
    }

    float Ar[16];
    #pragma unroll
    for (int n = 0; n < 16; n++) Ar[n] = -__expf(Alog[d*16 + n]);
    float A0 = Ar[0];
    bool st = true;
    #pragma unroll
    for (int n = 1; n < 16; n++)
        if (fabsf(Ar[n] - (float)(n+1)*A0) > 1e-4f * fabsf(Ar[n])) st = false;
    __syncthreads();

    float h[16];
    #pragma unroll
    for (int n = 0; n < 16; n++) h[n] = 0.f;
    float S = 0.f;
    const float4* bc = (const float4*)s_bc;
    #pragma unroll 4
    for (int t = 0; t < TCH; t++) {
        float del = s_del[t*D + d];
        float u   = s_u  [t*D + d];
        float du  = del * u;
        float4 b0 = bc[t*8+0], b1 = bc[t*8+1], b2 = bc[t*8+2], b3 = bc[t*8+3];
        float a[16];
        if (st) powers16(__expf(del*A0), a);
        else {
            #pragma unroll
            for (int n = 0; n < 16; n++) a[n] = __expf(del*Ar[n]);
        }
        h[0]=a[0]*h[0]+du*b0.x;  h[1]=a[1]*h[1]+du*b0.y;
        h[2]=a[2]*h[2]+du*b0.z;  h[3]=a[3]*h[3]+du*b0.w;
        h[4]=a[4]*h[4]+du*b1.x;  h[5]=a[5]*h[5]+du*b1.y;
        h[6]=a[6]*h[6]+du*b1.z;  h[7]=a[7]*h[7]+du*b1.w;
        h[8]=a[8]*h[8]+du*b2.x;  h[9]=a[9]*h[9]+du*b2.y;
        h[10]=a[10]*h[10]+du*b2.z; h[11]=a[11]*h[11]+du*b2.w;
        h[12]=a[12]*h[12]+du*b3.x; h[13]=a[13]*h[13]+du*b3.y;
        h[14]=a[14]*h[14]+du*b3.z; h[15]=a[15]*h[15]+du*b3.w;
        S += del;
    }
    float ap[16];
    if (st) powers16(__expf(S*A0), ap);
    else {
        #pragma unroll
        for (int n = 0; n < 16; n++) ap[n] = __expf(S*Ar[n]);
    }
    float4* o = (float4*)(Sum + (((size_t)s*NCHK + ch)*D + d)*32);
    float4* hv = (float4*)h;
    float4* av = (float4*)ap;
    #pragma unroll
    for (int n = 0; n < 4; n++) { o[n] = hv[n]; o[4+n] = av[n]; }
}

// ---------------- scan phase B: sequential prefix over chunks (both D) ------
__global__ void k_scanB()
{
    int tid = blockIdx.x * 256 + threadIdx.x;
    const float* Sum; float* Hin; int D;
    if (tid < 4*64*16) { Sum = g_SumM; Hin = g_HinM; D = 64; }
    else {
        tid -= 4*64*16;
        if (tid >= 4*128*16) return;
        Sum = g_SumG; Hin = g_HinG; D = 128;
    }
    int n = tid & 15;
    int d = (tid >> 4) % D;
    int s = tid / (D*16);
    size_t stride = (size_t)D*32;
    const float* sp = Sum + (((size_t)s*NCHK)*D + d)*32 + n;
    float* hp = Hin + (((size_t)s*NCHK)*D + d)*16 + n;
    float hin = 0.f;
    #pragma unroll 8
    for (int c = 0; c < NCHK; c++) {
        hp[(size_t)c*D*16] = hin;
        hin = sp[(size_t)c*stride + 16]*hin + sp[(size_t)c*stride];
    }
}

// ---------------- scan phase C: re-scan with carry, emit y (smem-staged) ----
template<int D>
__global__ void __launch_bounds__(D) k_scanC(
    const float* __restrict__ Alog, const float* __restrict__ Dp)
{
    __shared__ __align__(16) float s_del[TCH*D];
    __shared__ __align__(16) float s_u  [TCH*D];
    __shared__ __align__(16) float s_bc [TCH*32];
    const float* DEL = (D == 64) ? g_dm  : g_dg;
    const float* U   = (D == 64) ? g_Um  : g_Ug;
    const float* BCp = (D == 64) ? g_BCm : g_BCg;
    const float* Hin = (D == 64) ? g_HinM : g_HinG;
    float*       Y   = (D == 64) ? g_ym  : g_yg;
    int s = blockIdx.x, ch = blockIdx.y;
    int d = threadIdx.x;
    size_t base = (size_t)s*LSEQ + (size_t)ch*TCH;

    {
        const float4* gdel = (const float4*)(DEL + base*D);
        const float4* gu   = (const float4*)(U   + base*D);
        const float4* gbc  = (const float4*)(BCp + base*32);
        float4* sdel = (float4*)s_del;
        float4* sun  = (float4*)s_u;
        float4* sbc  = (float4*)s_bc;
        #pragma unroll
        for (int i = 0; i < TCH/4; i++) { int k = i*D + d; sdel[k] = gdel[k]; }
        #pragma unroll
        for (int i = 0; i < TCH/4; i++) { int k = i*D + d; sun[k] = gu[k]; }
        for (int k = d; k < TCH*8; k += D) sbc[k] = gbc[k];
    }

    float Ar[16];
    #pragma unroll
    for (int n = 0; n < 16; n++) Ar[n] = -__expf(Alog[d*16 + n]);
    float A0 = Ar[0];
    bool st = true;
    #pragma unroll
    for (int n = 1; n < 16; n++)
        if (fabsf(Ar[n] - (float)(n+1)*A0) > 1e-4f * fabsf(Ar[n])) st = false;

    float h[16];
    const float4* hp = (const float4*)(Hin + (((size_t)s*NCHK + ch)*D + d)*16);
    float4 h0 = hp[0], h1 = hp[1], h2 = hp[2], h3 = hp[3];
    h[0]=h0.x; h[1]=h0.y; h[2]=h0.z; h[3]=h0.w;
    h[4]=h1.x; h[5]=h1.y; h[6]=h1.z; h[7]=h1.w;
    h[8]=h2.x; h[9]=h2.y; h[10]=h2.z; h[11]=h2.w;
    h[12]=h3.x; h[13]=h3.y; h[14]=h3.z; h[15]=h3.w;
    float Dd = Dp[d];
    __syncthreads();

    const float4* bc = (const float4*)s_bc;
    float* yp = Y + base*D + d;
    #pragma unroll 4
    for (int t = 0; t < TCH; t++) {
        float del = s_del[t*D + d];
        float u   = s_u  [t*D + d];
        float du  = del * u;
        float4 b0 = bc[t*8+0], b1 = bc[t*8+1], b2 = bc[t*8+2], b3 = bc[t*8+3];
        float4 c0 = bc[t*8+4], c1 = bc[t*8+5], c2 = bc[t*8+6], c3 = bc[t*8+7];
        float a[16];
        if (st) powers16(__expf(del*A0), a);
        else {
            #pragma unroll
            for (int n = 0; n < 16; n++) a[n] = __expf(del*Ar[n]);
        }
        h[0]=a[0]*h[0]+du*b0.x;  h[1]=a[1]*h[1]+du*b0.y;
        h[2]=a[2]*h[2]+du*b0.z;  h[3]=a[3]*h[3]+du*b0.w;
        h[4]=a[4]*h[4]+du*b1.x;  h[5]=a[5]*h[5]+du*b1.y;
        h[6]=a[6]*h[6]+du*b1.z;  h[7]=a[7]*h[7]+du*b1.w;
        h[8]=a[8]*h[8]+du*b2.x;  h[9]=a[9]*h[9]+du*b2.y;
        h[10]=a[10]*h[10]+du*b2.z; h[11]=a[11]*h[11]+du*b2.w;
        h[12]=a[12]*h[12]+du*b3.x; h[13]=a[13]*h[13]+du*b3.y;
        h[14]=a[14]*h[14]+du*b3.z; h[15]=a[15]*h[15]+du*b3.w;
        float y = Dd*u;
        y += h[0]*c0.x + h[1]*c0.y + h[2]*c0.z + h[3]*c0.w;
        y += h[4]*c1.x + h[5]*c1.y + h[6]*c1.z + h[7]*c1.w;
        y += h[8]*c2.x + h[9]*c2.y + h[10]*c2.z + h[11]*c2.w;
        y += h[12]*c3.x + h[13]*c3.y + h[14]*c3.z + h[15]*c3.w;
        yp[(size_t)t*D] = y;
    }
}

// ---------------- output: o = (mixer ⊙ global) @ Wo^T + bo -------------------
__global__ void __launch_bounds__(256) k_out(
    const float* __restrict__ Wo, const float* __restrict__ bo,
    float* __restrict__ out)
{
    __shared__ __align__(16) float sp[64*132];
    int o = blockIdx.y >> 1, b = blockIdx.y & 1;
    int l0 = blockIdx.x * 64;
    int tid = threadIdx.x;

    int sm = (o == 0) ? b : 2 + b;
    int sg = (o == 0) ? 2 + b : b;
    const float* ym = g_ym + ((size_t)sm*LSEQ + l0)*64;
    const float* zz = g_Z  + ((size_t)sm*LSEQ + l0)*64;
    const float* yg = g_yg + ((size_t)sg*LSEQ + l0)*128;

    for (int i = tid; i < 64*128; i += 256) {
        int t = i >> 7, k = i & 127;
        float m = (k < 64) ? ym[t*64 + k] : zz[t*64 + (k-64)];
        sp[t*132 + k] = m * yg[t*128 + k];
    }
    __syncthreads();

    int tx = tid & 15, ty = tid >> 4;
    int ch0 = tx * 4, t0 = ty * 4;
    float acc[4][4];
    #pragma unroll
    for (int i = 0; i < 4; i++)
        #pragma unroll
        for (int j = 0; j < 4; j++) acc[i][j] = 0.f;

    const float4* p0 = (const float4*)(sp + (t0+0)*132);
    const float4* p1 = (const float4*)(sp + (t0+1)*132);
    const float4* p2 = (const float4*)(sp + (t0+2)*132);
    const float4* p3 = (const float4*)(sp + (t0+3)*132);
    const float4* w0 = (const float4*)(Wo + (ch0+0)*128);
    const float4* w1 = (const float4*)(Wo + (ch0+1)*128);
    const float4* w2 = (const float4*)(Wo + (ch0+2)*128);
    const float4* w3 = (const float4*)(Wo + (ch0+3)*128);
    #pragma unroll 8
    for (int k4 = 0; k4 < 32; k4++) {
        float4 pv[4] = { p0[k4], p1[k4], p2[k4], p3[k4] };
        float4 wv[4] = { __ldg(w0+k4), __ldg(w1+k4), __ldg(w2+k4), __ldg(w3+k4) };
        #pragma unroll
        for (int i = 0; i < 4; i++)
            #pragma unroll
            for (int j = 0; j < 4; j++)
                acc[i][j] += pv[i].x*wv[j].x + pv[i].y*wv[j].y
                           + pv[i].z*wv[j].z + pv[i].w*wv[j].w;
    }
    float* op = out + ((size_t)o*2 + b)*64*LSEQ;
    #pragma unroll
    for (int j = 0; j < 4; j++) {
        float bj = bo[ch0 + j];
        float4 v = { acc[0][j]+bj, acc[1][j]+bj, acc[2][j]+bj, acc[3][j]+bj };
        *(float4*)(op + (size_t)(ch0+j)*LSEQ + l0 + t0) = v;
    }
}

// -----------------------------------------------------------------------------
extern "C" void kernel_launch(void* const* d_in, const int* in_sizes, int n_in,
                              void* d_out, int out_size)
{
    const float* f1    = (const float*)d_in[0];
    const float* f2    = (const float*)d_in[1];
    const float* Wi    = (const float*)d_in[2];
    const float* bi    = (const float*)d_in[3];
    const float* wcx   = (const float*)d_in[4];
    const float* bcx   = (const float*)d_in[5];
    const float* wcz   = (const float*)d_in[6];
    const float* bcz   = (const float*)d_in[7];
    const float* Wxp_m = (const float*)d_in[8];
    const float* Wdt_m = (const float*)d_in[9];
    const float* bdt_m = (const float*)d_in[10];
    const float* Alog_m= (const float*)d_in[11];
    const float* Dm    = (const float*)d_in[12];
    const float* Wg    = (const float*)d_in[13];
    const float* bg    = (const float*)d_in[14];
    const float* ln_g  = (const float*)d_in[15];
    const float* ln_b  = (const float*)d_in[16];
    const float* wcg   = (const float*)d_in[17];
    const float* bcg   = (const float*)d_in[18];
    const float* Wxp_g = (const float*)d_in[19];
    const float* Wdt_g = (const float*)d_in[20];
    const float* bdt_g = (const float*)d_in[21];
    const float* Alog_g= (const float*)d_in[22];
    const float* Dg    = (const float*)d_in[23];
    const float* Wo    = (const float*)d_in[24];
    const float* bo    = (const float*)d_in[25];
    float* out = (float*)d_out;

    k_mixer_front <<<dim3(4, LSEQ/64), 128>>>(f1, f2, Wi, bi, wcx, bcx, wcz, bcz,
                                              Wxp_m, Wdt_m, bdt_m);
    k_global_front<<<dim3(4, LSEQ/32), 128>>>(f1, f2, Wg, bg, ln_g, ln_b, wcg, bcg,
                                              Wxp_g, Wdt_g, bdt_g);
    k_scanA<64>  <<<dim3(4, NCHK),  64>>>(Alog_m);
    k_scanA<128> <<<dim3(4, NCHK), 128>>>(Alog_g);
    k_scanB      <<<(4*64*16 + 4*128*16 + 255)/256, 256>>>();
    k_scanC<64>  <<<dim3(4, NCHK),  64>>>(Alog_m, Dm);
    k_scanC<128> <<<dim3(4, NCHK), 128>>>(Alog_g, Dg);
    k_out        <<<dim3(LSEQ/64, 4), 256>>>(Wo, bo, out);
}